// round 12
// baseline (speedup 1.0000x reference)
#include <cuda_runtime.h>
#include <cooperative_groups.h>

namespace cg = cooperative_groups;

#define BB 4
#define SS 2048
#define HH 16
#define NPAIR 64
#define NBLK 256
#define NTHR 256
#define L2E 1.44269504088896340736f

// Scratch (device globals; no allocation allowed).
__device__ float  g_q [NPAIR*SS];      // q * log2(e), [pair][s]
__device__ float2 g_kv[NPAIR*SS];      // (k, v) interleaved, [pair][s]
__device__ float  g_o [BB*SS*HH];      // attention output, [b][s][h]

__device__ __forceinline__ float ex2f(float x) {
    float r; asm("ex2.approx.ftz.f32 %0, %1;" : "=f"(r) : "f"(x)); return r;
}

// ---------------------------------------------------------------------------
// Single cooperative kernel: qkv -> grid.sync -> attention -> grid.sync -> proj.
// Grid 256 x 256. Driver validates co-residency (2 blocks/SM needed).
//
// Attention balance: thread owns queries i1 = l and i2 = 2047 - l for its
// (b,h) pair -> exactly 2049 exps per thread, identical for every thread,
// block, and SM. No tail, no heavy/light imbalance.
// ---------------------------------------------------------------------------
__global__ void __launch_bounds__(NTHR) fused_kernel(
    const float* __restrict__ x,   // [8192, 16]
    const float* __restrict__ wq,  // [16, 48]
    const float* __restrict__ bq,  // [48]
    const float* __restrict__ wo,  // [16, 16]
    const float* __restrict__ bo,  // [16]
    float* __restrict__ out)       // [8192, 16]
{
    __shared__ float2 skv[SS];         // 16 KB (phase B)
    __shared__ float  so[512];         // phase C staging
    __shared__ float  sw[256];
    __shared__ float  sb[16];

    cg::grid_group grid = cg::this_grid();
    int t  = threadIdx.x;
    int bx = blockIdx.x;

    // ---------------- Phase A: qkv projection -----------------------------
    // Item g = pair*2048 + s. Each thread: items g0 and g0 + 65536.
    #pragma unroll
    for (int kk = 0; kk < 2; ++kk) {
        int g = bx * NTHR + t + kk * (NBLK * NTHR);
        int pair = g >> 11, s = g & (SS - 1);
        int b = pair >> 4, h = pair & 15;
        const float4* xr = reinterpret_cast<const float4*>(x + (b * SS + s) * 16);
        float4 x0 = xr[0], x1 = xr[1], x2 = xr[2], x3 = xr[3];
        float xv[16] = { x0.x, x0.y, x0.z, x0.w, x1.x, x1.y, x1.z, x1.w,
                         x2.x, x2.y, x2.z, x2.w, x3.x, x3.y, x3.z, x3.w };
        float aq = bq[h], ak = bq[h + 16], av = bq[h + 32];
        #pragma unroll
        for (int d = 0; d < 16; ++d) {
            float xd = xv[d];
            aq = fmaf(xd, wq[d * 48 + h],      aq);   // h warp-uniform -> broadcast
            ak = fmaf(xd, wq[d * 48 + h + 16], ak);
            av = fmaf(xd, wq[d * 48 + h + 32], av);
        }
        g_q[g]  = aq * L2E;                // scale=1, fold log2(e)
        g_kv[g] = make_float2(ak, av);     // coalesced STG.64
    }
    grid.sync();

    // ---------------- Phase B: causal attention (mirror-paired) -----------
    {
        int pair = bx >> 2;                        // 4 blocks per pair
        int l    = ((bx & 3) << 8) + t;            // 0..1023
        int i1   = l;                              // query 1
        int i2   = (SS - 1) - l;                   // query 2 (mirror)

        // Stage full (k,v)[0..2047] for this pair.
        {
            const float4* src = reinterpret_cast<const float4*>(g_kv + pair * SS);
            float4* dst = reinterpret_cast<float4*>(skv);
            #pragma unroll
            for (int u = 0; u < 4; ++u) dst[t + u * NTHR] = src[t + u * NTHR];
        }
        __syncthreads();

        float qa = g_q[pair * SS + i1];
        float qb = g_q[pair * SS + i2];

        float da0 = 0.f, da1 = 0.f, na0 = 0.f, na1 = 0.f;
        float db0 = 0.f, db1 = 0.f, nb0 = 0.f, nb1 = 0.f;

        // Dual segment: j in [0, i1] serves both queries (j <= i1 < i2).
        int j = 0;
        #pragma unroll 2
        for (; j < i1; j += 2) {                   // covers j, j+1 (both <= i1)
            float2 A = skv[j];
            float2 C = skv[j + 1];
            float ea0 = ex2f(qa * A.x);
            float ea1 = ex2f(qa * C.x);
            float eb0 = ex2f(qb * A.x);
            float eb1 = ex2f(qb * C.x);
            da0 += ea0;  na0 = fmaf(ea0, A.y, na0);
            da1 += ea1;  na1 = fmaf(ea1, C.y, na1);
            db0 += eb0;  nb0 = fmaf(eb0, A.y, nb0);
            db1 += eb1;  nb1 = fmaf(eb1, C.y, nb1);
        }
        if (j == i1) {                             // diagonal when i1 even
            float2 A = skv[j];
            float ea = ex2f(qa * A.x);
            float eb = ex2f(qb * A.x);
            da0 += ea;  na0 = fmaf(ea, A.y, na0);
            db0 += eb;  nb0 = fmaf(eb, A.y, nb0);
            ++j;
        }
        // Single segment: j in (i1, i2] for query 2 only (count 2047-2l, odd).
        #pragma unroll 4
        for (; j + 1 <= i2; j += 2) {
            float2 A = skv[j];
            float2 C = skv[j + 1];
            float e0 = ex2f(qb * A.x);
            float e1 = ex2f(qb * C.x);
            db0 += e0;  nb0 = fmaf(e0, A.y, nb0);
            db1 += e1;  nb1 = fmaf(e1, C.y, nb1);
        }
        if (j <= i2) {
            float2 A = skv[j];
            float e = ex2f(qb * A.x);
            db0 += e;  nb0 = fmaf(e, A.y, nb0);
        }

        int b = pair >> 4, h = pair & 15;
        g_o[(b * SS + i1) * HH + h] = (na0 + na1) / (da0 + da1);
        g_o[(b * SS + i2) * HH + h] = (nb0 + nb1) / (db0 + db1);
    }
    grid.sync();

    // ---------------- Phase C: output projection --------------------------
    // Block handles 512 consecutive output elements (32 rows).
    {
        so[t]       = g_o[bx * 512 + t];           // coalesced
        so[t + 256] = g_o[bx * 512 + 256 + t];
        sw[t] = wo[t];
        if (t < 16) sb[t] = bo[t];
        __syncthreads();

        #pragma unroll
        for (int u = 0; u < 2; ++u) {
            int e  = u * 256 + t;                  // local element 0..511
            int rl = e >> 4, c = e & 15;
            float acc = sb[c];
            #pragma unroll
            for (int d = 0; d < 16; ++d)
                acc = fmaf(so[rl * 16 + d], sw[d * 16 + c], acc);
            out[bx * 512 + e] = acc;               // coalesced
        }
    }
}

// ---------------------------------------------------------------------------
extern "C" void kernel_launch(void* const* d_in, const int* in_sizes, int n_in,
                              void* d_out, int out_size)
{
    const float* x     = (const float*)d_in[0];
    const float* w_qkv = (const float*)d_in[1];
    const float* b_qkv = (const float*)d_in[2];
    const float* w_out = (const float*)d_in[3];
    const float* b_out = (const float*)d_in[4];
    float* out = (float*)d_out;

    void* args[] = { (void*)&x, (void*)&w_qkv, (void*)&b_qkv,
                     (void*)&w_out, (void*)&b_out, (void*)&out };
    cudaLaunchCooperativeKernel((const void*)fused_kernel,
                                dim3(NBLK), dim3(NTHR), args, 0, (cudaStream_t)0);
}

// round 13
// speedup vs baseline: 1.0494x; 1.0494x over previous
#include <cuda_runtime.h>
#include <cooperative_groups.h>

namespace cg = cooperative_groups;

#define BB 4
#define SS 2048
#define HH 16
#define NPAIR 64
#define NBLK 592               // 148 SMs x 4 blocks, exact
#define NTHR 128
#define NTICK 1024             // 64 pairs x 16 query tiles
#define L2E 1.44269504088896340736f

// Scratch (device globals; no allocation allowed).
__device__ float  g_q [NPAIR*SS];      // q * log2(e), [pair][s]
__device__ float2 g_kv[NPAIR*SS];      // (k, v) interleaved, [pair][s]
__device__ float  g_o [BB*SS*HH];      // attention output, [b][s][h]
__device__ unsigned int g_ticket;      // reset each run in phase A

__device__ __forceinline__ float ex2f(float x) {
    float r; asm("ex2.approx.ftz.f32 %0, %1;" : "=f"(r) : "f"(x)); return r;
}

// ---------------------------------------------------------------------------
// Single cooperative kernel, grid 592x128 (exactly 4 blocks on each SM).
//   Phase A: qkv projection (grid-stride), reset ticket counter.
//   Phase B: causal attention; 1024 uniform-query tiles pulled heavy-first
//            from an atomic ticket counter (LPT schedule -> SM balance).
//   Phase C: output projection (grid-stride chunks).
// ---------------------------------------------------------------------------
__global__ void __launch_bounds__(NTHR) fused_kernel(
    const float* __restrict__ x,   // [8192, 16]
    const float* __restrict__ wq,  // [16, 48]
    const float* __restrict__ bq,  // [48]
    const float* __restrict__ wo,  // [16, 16]
    const float* __restrict__ bo,  // [16]
    float* __restrict__ out)       // [8192, 16]
{
    __shared__ float2 skv[SS];             // 16 KB
    __shared__ float  sc[NTHR];            // phase C staging
    __shared__ unsigned int stk;

    cg::grid_group grid = cg::this_grid();
    int t  = threadIdx.x;
    int bx = blockIdx.x;

    // ---------------- Phase A: qkv projection (grid-stride) ---------------
    for (int g = bx * NTHR + t; g < NPAIR * SS; g += NBLK * NTHR) {
        int pair = g >> 11, s = g & (SS - 1);
        int b = pair >> 4, h = pair & 15;
        const float4* xr = reinterpret_cast<const float4*>(x + (b * SS + s) * 16);
        float4 x0 = xr[0], x1 = xr[1], x2 = xr[2], x3 = xr[3];
        float xv[16] = { x0.x, x0.y, x0.z, x0.w, x1.x, x1.y, x1.z, x1.w,
                         x2.x, x2.y, x2.z, x2.w, x3.x, x3.y, x3.z, x3.w };
        float aq = bq[h], ak = bq[h + 16], av = bq[h + 32];
        #pragma unroll
        for (int d = 0; d < 16; ++d) {
            float xd = xv[d];
            aq = fmaf(xd, wq[d * 48 + h],      aq);   // h warp-uniform
            ak = fmaf(xd, wq[d * 48 + h + 16], ak);
            av = fmaf(xd, wq[d * 48 + h + 32], av);
        }
        g_q[g]  = aq * L2E;                // scale=1, fold log2(e)
        g_kv[g] = make_float2(ak, av);     // coalesced STG.64
    }
    if (bx == 0 && t == 0) g_ticket = 0;   // reset for this (replayed) run
    grid.sync();

    // ---------------- Phase B: causal attention (LPT tickets) -------------
    for (;;) {
        if (t == 0) stk = atomicAdd(&g_ticket, 1u);
        __syncthreads();
        unsigned int tk = stk;
        if (tk >= NTICK) break;

        int pair = tk & (NPAIR - 1);
        int tile = 15 - (int)(tk >> 6);    // heavy tiles first (LPT)
        int tile_end = (tile + 1) << 7;

        // Stage (k,v) prefix [0, tile_end).
        {
            const float4* src = reinterpret_cast<const float4*>(g_kv + pair * SS);
            float4* dst = reinterpret_cast<float4*>(skv);
            int n4 = tile_end >> 1;
            for (int j = t; j < n4; j += NTHR) dst[j] = src[j];
        }
        __syncthreads();

        int   i  = (tile << 7) + t;
        float qi = g_q[pair * SS + i];

        float den0 = 0.f, den1 = 0.f, num0 = 0.f, num1 = 0.f;
        int j = 0;
        #pragma unroll 4
        for (; j < i; j += 2) {            // j, j+1 both <= i
            float2 a = skv[j];
            float2 c = skv[j + 1];
            float e0 = ex2f(qi * a.x);
            float e1 = ex2f(qi * c.x);
            den0 += e0;  num0 = fmaf(e0, a.y, num0);
            den1 += e1;  num1 = fmaf(e1, c.y, num1);
        }
        if (j == i) {                      // diagonal when i even
            float2 a = skv[j];
            float e = ex2f(qi * a.x);
            den0 += e;  num0 = fmaf(e, a.y, num0);
        }

        int b = pair >> 4, h = pair & 15;
        g_o[(b * SS + i) * HH + h] = (num0 + num1) / (den0 + den1);
        __syncthreads();                   // protect skv before restage
    }
    grid.sync();

    // ---------------- Phase C: output projection (grid-stride) ------------
    {
        int c = t & 15;                    // loop-invariant output column
        float wcol[16];
        #pragma unroll
        for (int d = 0; d < 16; ++d) wcol[d] = wo[d * 16 + c];
        float bc = bo[c];

        for (int chunk = bx; chunk < (BB * SS * HH) / NTHR; chunk += NBLK) {
            sc[t] = g_o[chunk * NTHR + t];     // coalesced (8 rows)
            __syncthreads();
            int rl = t >> 4;
            float acc = bc;
            #pragma unroll
            for (int d = 0; d < 16; ++d)
                acc = fmaf(sc[rl * 16 + d], wcol[d], acc);
            out[chunk * NTHR + t] = acc;       // coalesced
            __syncthreads();
        }
    }
}

// ---------------------------------------------------------------------------
extern "C" void kernel_launch(void* const* d_in, const int* in_sizes, int n_in,
                              void* d_out, int out_size)
{
    const float* x     = (const float*)d_in[0];
    const float* w_qkv = (const float*)d_in[1];
    const float* b_qkv = (const float*)d_in[2];
    const float* w_out = (const float*)d_in[3];
    const float* b_out = (const float*)d_in[4];
    float* out = (float*)d_out;

    void* args[] = { (void*)&x, (void*)&w_qkv, (void*)&b_qkv,
                     (void*)&w_out, (void*)&b_out, (void*)&out };
    cudaLaunchCooperativeKernel((const void*)fused_kernel,
                                dim3(NBLK), dim3(NTHR), args, 0, (cudaStream_t)0);
}